// round 11
// baseline (speedup 1.0000x reference)
#include <cuda_runtime.h>
#include <cuda_fp16.h>
#include <cstdint>

// Problem constants
#define S_LEN 2048
#define BATCH 2
#define EMBED 1024
#define HEADS 16
#define HDIM  64
#define M_ROWS (S_LEN * BATCH)        // 4096
#define QKV_COLS (3 * EMBED)          // 3072

// Q scale folded with log2(e) so softmax can use exp2 directly
#define QSCALE 0.18033688011112042f   // 0.125 * log2(e)
#define ONES_H2 0x3C003C00u           // half2(1.0, 1.0)

// ---------------------------------------------------------------------------
// Scratch (device globals; no allocation in kernel_launch)
// ---------------------------------------------------------------------------
__device__ __align__(16) __half g_xh[(size_t)M_ROWS * EMBED];
__device__ __align__(16) __half g_w1h[(size_t)QKV_COLS * EMBED];
__device__ __align__(16) __half g_w2h[(size_t)EMBED * EMBED];
__device__ __align__(16) __half g_qkvh[(size_t)M_ROWS * QKV_COLS];
__device__ __align__(16) __half g_ah[(size_t)M_ROWS * EMBED];

// ---------------------------------------------------------------------------
// PTX helpers (baseline compute_103-safe: mma.sync + ldmatrix + cp.async)
// ---------------------------------------------------------------------------
__device__ __forceinline__ uint32_t smem_u32(const void* p) {
    uint32_t addr;
    asm("{ .reg .u64 t; cvta.to.shared.u64 t, %1; cvt.u32.u64 %0, t; }"
        : "=r"(addr) : "l"(p));
    return addr;
}

__device__ __forceinline__ void cp16(uint32_t dst, const void* src) {
    asm volatile("cp.async.cg.shared.global [%0], [%1], 16;" :: "r"(dst), "l"(src));
}
#define CP_COMMIT() asm volatile("cp.async.commit_group;" ::: "memory")
#define CP_WAIT1()  asm volatile("cp.async.wait_group 1;" ::: "memory")
#define CP_WAIT2()  asm volatile("cp.async.wait_group 2;" ::: "memory")

#define LDSM_X4(r0, r1, r2, r3, addr) \
    asm volatile("ldmatrix.sync.aligned.m8n8.x4.shared.b16 {%0,%1,%2,%3}, [%4];" \
        : "=r"(r0), "=r"(r1), "=r"(r2), "=r"(r3) : "r"(addr))

#define LDSM_X4_T(r0, r1, r2, r3, addr) \
    asm volatile("ldmatrix.sync.aligned.m8n8.x4.trans.shared.b16 {%0,%1,%2,%3}, [%4];" \
        : "=r"(r0), "=r"(r1), "=r"(r2), "=r"(r3) : "r"(addr))

__device__ __forceinline__ void mma16816(float* c, const uint32_t* a,
                                         const uint32_t b0, const uint32_t b1) {
    asm volatile(
        "mma.sync.aligned.m16n8k16.row.col.f32.f16.f16.f32 "
        "{%0,%1,%2,%3}, {%4,%5,%6,%7}, {%8,%9}, {%0,%1,%2,%3};"
        : "+f"(c[0]), "+f"(c[1]), "+f"(c[2]), "+f"(c[3])
        : "r"(a[0]), "r"(a[1]), "r"(a[2]), "r"(a[3]), "r"(b0), "r"(b1));
}

__device__ __forceinline__ float fast_exp2(float x) {
    float y;
    asm("ex2.approx.f32 %0, %1;" : "=f"(y) : "f"(x));
    return y;
}

__device__ __forceinline__ uint32_t pack_f16(float f0, float f1) {
    __half2 h = __floats2half2_rn(f0, f1);
    return *reinterpret_cast<uint32_t*>(&h);
}

// pack two fp32 and take exp2 in half2 (one cvt + one MUFU for 2 elements)
__device__ __forceinline__ uint32_t exp2_f16x2(float f0, float f1) {
    uint32_t h = pack_f16(f0, f1);
    uint32_t y;
    asm("ex2.approx.f16x2 %0, %1;" : "=r"(y) : "r"(h));
    return y;
}

// ---------------------------------------------------------------------------
// fused fp32 -> fp16 convert for x, Win, Wout in ONE launch
// sizes in float4 units: x 1048576, w1 786432, w2 262144
// ---------------------------------------------------------------------------
#define CVT_X4  1048576
#define CVT_W14 786432
#define CVT_W24 262144
#define CVT_TOT (CVT_X4 + CVT_W14 + CVT_W24)   // 2097152

__global__ __launch_bounds__(256) void cvt_all_kernel(
    const float4* __restrict__ x, const float4* __restrict__ w1,
    const float4* __restrict__ w2, uint2* __restrict__ xh,
    uint2* __restrict__ w1h, uint2* __restrict__ w2h)
{
    int i = blockIdx.x * blockDim.x + threadIdx.x;
    const float4* in;
    uint2* out;
    int j;
    if (i < CVT_X4) {
        in = x; out = xh; j = i;
    } else if (i < CVT_X4 + CVT_W14) {
        in = w1; out = w1h; j = i - CVT_X4;
    } else {
        in = w2; out = w2h; j = i - CVT_X4 - CVT_W14;
    }
    float4 v = in[j];
    uint2 r;
    r.x = pack_f16(v.x, v.y);
    r.y = pack_f16(v.z, v.w);
    out[j] = r;
}

// ---------------------------------------------------------------------------
// mma.sync fp16 GEMM (PERSISTENT):  C[M,Ntot] = A[M,1024]*W[Ntot,1024]^T + b
// CTA tile 128x256, 16 warps (4 M x 4 N), warp tile 32x64, 512 threads.
// Persistent CTAs: grid = min(tiles, 148); the 3-buffer cp.async ring runs
// continuously ACROSS tiles (no pipeline drain between tiles).
// Columns < qcols scaled by QSCALE.
// ---------------------------------------------------------------------------
#define GK 1024
#define KSTEP 64
#define NSTAGE (GK / KSTEP)          // 16
#define STAGE_BYTES 49152            // A 16KB + W 32KB
#define GEMM_SMEM (3 * STAGE_BYTES)  // 147456

__global__ __launch_bounds__(512, 1) void gemm_mma_kernel(
    const __half* __restrict__ A, const __half* __restrict__ W,
    const float* __restrict__ bias, float* __restrict__ Cf,
    __half* __restrict__ Ch, int Ntot, int qcols, int ntiles, int ncols)
{
    extern __shared__ char sm_raw[];
    const uint32_t smem_base = smem_u32(sm_raw);
    const int tid = threadIdx.x;
    const int wid = tid >> 5;
    const int lane = tid & 31;
    const int warpM = wid & 3;          // 4 warps over M (32 rows each)
    const int warpN = wid >> 2;         // 4 warps over N (64 cols each)

    // load one K-stage of tile tl into ring buffer buf
    auto load_stage = [&](int tl, int s, int buf) {
        const int rowBase = (tl / ncols) * 128;
        const int colBase = (tl % ncols) * 256;
        const int k0 = s * KSTEP;
        const uint32_t base = smem_base + (uint32_t)buf * STAGE_BYTES;
#pragma unroll
        for (int i = 0; i < 6; i++) {
            int idx = tid + (i << 9);          // 0..3071
            if (idx < 1024) {
                int r = idx >> 3, c16 = idx & 7;
                const void* src = A + (size_t)(rowBase + r) * GK + k0 + c16 * 8;
                cp16(base + (uint32_t)(r * 128 + ((c16 ^ (r & 7)) * 16)), src);
            } else {
                int idx2 = idx - 1024;         // 0..2047
                int r = idx2 >> 3, c16 = idx2 & 7;
                const void* src = W + (size_t)(colBase + r) * GK + k0 + c16 * 8;
                cp16(base + 16384u + (uint32_t)(r * 128 + ((c16 ^ (r & 7)) * 16)),
                     src);
            }
        }
    };

    const int aRow = warpM * 32 + (lane & 15);
    const int aHalf = lane >> 4;
    const int bRow = warpN * 64 + ((lane >> 4) * 8) + (lane & 7);
    const int bHalf = (lane >> 3) & 1;

    // prologue: first two stages of this CTA's first tile
    load_stage(blockIdx.x, 0, 0); CP_COMMIT();
    load_stage(blockIdx.x, 1, 1); CP_COMMIT();

    int buf = 0;
    for (int tl = blockIdx.x; tl < ntiles; tl += gridDim.x) {
        float acc[2][8][4];
#pragma unroll
        for (int mi = 0; mi < 2; mi++)
#pragma unroll
            for (int ni = 0; ni < 8; ni++)
#pragma unroll
                for (int j = 0; j < 4; j++) acc[mi][ni][j] = 0.f;

        for (int s = 0; s < NSTAGE; s++) {
            CP_WAIT1();
            __syncthreads();
            // prefetch stage s+2 (possibly of the NEXT tile this CTA owns)
            {
                int nbuf = buf + 2; if (nbuf >= 3) nbuf -= 3;
                int gs = s + 2;
                if (gs < NSTAGE) {
                    load_stage(tl, gs, nbuf);
                } else {
                    int tn = tl + gridDim.x;
                    if (tn < ntiles) load_stage(tn, gs - NSTAGE, nbuf);
                }
                CP_COMMIT();   // commit every stage (may be empty) to keep counts
            }

            const uint32_t base = smem_base + (uint32_t)buf * STAGE_BYTES;
#pragma unroll
            for (int kk = 0; kk < 4; kk++) {
                uint32_t a[2][4], b[4][4];
#pragma unroll
                for (int mi = 0; mi < 2; mi++) {
                    int r = aRow + mi * 16;
                    int c16 = kk * 2 + aHalf;
                    uint32_t off = (uint32_t)(r * 128 + ((c16 ^ (r & 7)) * 16));
                    LDSM_X4(a[mi][0], a[mi][1], a[mi][2], a[mi][3], base + off);
                }
#pragma unroll
                for (int np = 0; np < 4; np++) {
                    int r = bRow + np * 16;
                    int c16 = kk * 2 + bHalf;
                    uint32_t off = (uint32_t)(r * 128 + ((c16 ^ (r & 7)) * 16));
                    LDSM_X4(b[np][0], b[np][1], b[np][2], b[np][3],
                            base + 16384u + off);
                }
#pragma unroll
                for (int mi = 0; mi < 2; mi++)
#pragma unroll
                    for (int ni = 0; ni < 8; ni++) {
                        const int np = ni >> 1, sub = (ni & 1) * 2;
                        mma16816(acc[mi][ni], a[mi], b[np][sub], b[np][sub + 1]);
                    }
            }
            if (++buf >= 3) buf = 0;
        }

        // epilogue for tile tl (ring keeps loading next tile in background)
        const int erow = (tl / ncols) * 128 + warpM * 32 + (lane >> 2);
        const int ecol0 = (tl % ncols) * 256 + warpN * 64 + (lane & 3) * 2;
#pragma unroll
        for (int ni = 0; ni < 8; ni++) {
            const int col = ecol0 + ni * 8;
            const float sc = (col < qcols) ? QSCALE : 1.f;
            const float bx = bias[col], by = bias[col + 1];
#pragma unroll
            for (int mi = 0; mi < 2; mi++) {
                const int r0 = erow + mi * 16;
                float v0 = (acc[mi][ni][0] + bx) * sc;
                float v1 = (acc[mi][ni][1] + by) * sc;
                float v2 = (acc[mi][ni][2] + bx) * sc;
                float v3 = (acc[mi][ni][3] + by) * sc;
                if (Cf) {
                    *(float2*)&Cf[(size_t)r0 * Ntot + col] = make_float2(v0, v1);
                    *(float2*)&Cf[(size_t)(r0 + 8) * Ntot + col] = make_float2(v2, v3);
                } else {
                    *(uint32_t*)&Ch[(size_t)r0 * Ntot + col] = pack_f16(v0, v1);
                    *(uint32_t*)&Ch[(size_t)(r0 + 8) * Ntot + col] = pack_f16(v2, v3);
                }
            }
        }
    }
}

// ---------------------------------------------------------------------------
// Flash attention on mma.sync fp16, exp2 in f16x2, row-sums via ones-MMA.
// grid (S/128, B*H), 256 threads (8 warps x 16 q rows each).
// KV chunk = 64 rows; 3-buffer cp.async ring, ONE barrier per chunk.
// smem 64KB; __launch_bounds__(256,2) targets 2 CTAs/SM (<=128 regs).
// (round-9 proven config)
// ---------------------------------------------------------------------------
#define FL_SMEM 65536
#define NCHUNK (S_LEN / 64)   // 32

__global__ __launch_bounds__(256, 2) void flash_mma_kernel(
    const __half* __restrict__ qkv, __half* __restrict__ oh)
{
    extern __shared__ char sm_raw[];
    const uint32_t sb = smem_u32(sm_raw);
    const int tid = threadIdx.x;
    const int wid = tid >> 5;
    const int lane = tid & 31;
    const int q0 = blockIdx.x * 128;
    const int b = blockIdx.y >> 4;
    const int h = blockIdx.y & 15;
    const int qcol = h * HDIM;
    const int kcol = EMBED + h * HDIM;
    const int vcol = 2 * EMBED + h * HDIM;

    // ---- load Q tile: 1024 cp16 (group 0) ----
#pragma unroll
    for (int i = 0; i < 4; i++) {
        int idx = tid + (i << 8);
        int r = idx >> 3;
        int c16 = idx & 7;
        const void* src = qkv + (size_t)((q0 + r) * 2 + b) * QKV_COLS + qcol + c16 * 8;
        cp16(sb + (uint32_t)(r * 128 + ((c16 ^ (r & 7)) * 16)), src);
    }
    CP_COMMIT();

    auto load_kv = [&](int j0, int buf) {
        const uint32_t base = sb + 16384u + (uint32_t)buf * 16384u;
#pragma unroll
        for (int i = 0; i < 4; i++) {
            int idx = tid + (i << 8);
            int mat = idx >> 9;             // 0:K 1:V
            int r = (idx >> 3) & 63;
            int c16 = idx & 7;
            int colb = mat ? vcol : kcol;
            const void* src = qkv + (size_t)((j0 + r) * 2 + b) * QKV_COLS + colb + c16 * 8;
            uint32_t dst = base + (uint32_t)(mat * 8192 + r * 128 +
                                             ((c16 ^ (r & 7)) * 16));
            cp16(dst, src);
        }
    };

    load_kv(0, 0);  CP_COMMIT();
    load_kv(64, 1); CP_COMMIT();

    CP_WAIT2();      // Q resident
    __syncthreads();

    // ---- Q fragments into registers ----
    uint32_t aq[4][4];
    {
        int r = wid * 16 + (lane & 15);
#pragma unroll
        for (int kk = 0; kk < 4; kk++) {
            int c16 = kk * 2 + (lane >> 4);
            uint32_t off = (uint32_t)(r * 128 + ((c16 ^ (r & 7)) * 16));
            LDSM_X4(aq[kk][0], aq[kk][1], aq[kk][2], aq[kk][3], sb + off);
        }
    }

    float O[8][4];
#pragma unroll
    for (int ni = 0; ni < 8; ni++)
#pragma unroll
        for (int j = 0; j < 4; j++) O[ni][j] = 0.f;
    float m0 = -1e30f, m1 = -1e30f, l0 = 0.f, l1 = 0.f;

    int buf = 0;
    for (int s = 0; s < NCHUNK; s++) {
        CP_WAIT1();
        __syncthreads();
        if (s + 2 < NCHUNK) {
            int nbuf = buf + 2; if (nbuf >= 3) nbuf -= 3;
            load_kv((s + 2) * 64, nbuf);
            CP_COMMIT();
        }

        const uint32_t kb = sb + 16384u + (uint32_t)buf * 16384u;

        // ---- QK^T ----
        float sc[8][4];
#pragma unroll
        for (int ni = 0; ni < 8; ni++)
#pragma unroll
            for (int j = 0; j < 4; j++) sc[ni][j] = 0.f;

#pragma unroll
        for (int kk = 0; kk < 4; kk++) {
            uint32_t kf[4][4];
            int rb = ((lane >> 4) * 8) + (lane & 7);
            int c16 = kk * 2 + ((lane >> 3) & 1);
#pragma unroll
            for (int np = 0; np < 4; np++) {
                int r = rb + np * 16;
                uint32_t off = (uint32_t)(r * 128 + ((c16 ^ (r & 7)) * 16));
                LDSM_X4(kf[np][0], kf[np][1], kf[np][2], kf[np][3], kb + off);
            }
#pragma unroll
            for (int ni = 0; ni < 8; ni++) {
                const int np = ni >> 1, sub = (ni & 1) * 2;
                mma16816(sc[ni], aq[kk], kf[np][sub], kf[np][sub + 1]);
            }
        }

        // ---- max/alpha bookkeeping (fp32) ----
        float mn0, mn1, alpha0, alpha1;
        {
            float mx = -1e30f;
#pragma unroll
            for (int ni = 0; ni < 8; ni++)
                mx = fmaxf(mx, fmaxf(sc[ni][0], sc[ni][1]));
            mx = fmaxf(mx, __shfl_xor_sync(0xffffffffu, mx, 1));
            mx = fmaxf(mx, __shfl_xor_sync(0xffffffffu, mx, 2));
            mn0 = fmaxf(m0, mx);
            alpha0 = fast_exp2(m0 - mn0);
            m0 = mn0;
        }
        {
            float mx = -1e30f;
#pragma unroll
            for (int ni = 0; ni < 8; ni++)
                mx = fmaxf(mx, fmaxf(sc[ni][2], sc[ni][3]));
            mx = fmaxf(mx, __shfl_xor_sync(0xffffffffu, mx, 1));
            mx = fmaxf(mx, __shfl_xor_sync(0xffffffffu, mx, 2));
            mn1 = fmaxf(m1, mx);
            alpha1 = fast_exp2(m1 - mn1);
            m1 = mn1;
        }
#pragma unroll
        for (int ni = 0; ni < 8; ni++) {
            O[ni][0] *= alpha0; O[ni][1] *= alpha0;
            O[ni][2] *= alpha1; O[ni][3] *= alpha1;
        }

        // ---- P (fp16 exp2) @ V, row sums via ones-MMA ----
        float sumacc[4] = {0.f, 0.f, 0.f, 0.f};
#pragma unroll
        for (int kk2 = 0; kk2 < 4; kk2++) {
            uint32_t p[4];
            p[0] = exp2_f16x2(sc[2 * kk2][0] - mn0,     sc[2 * kk2][1] - mn0);
            p[1] = exp2_f16x2(sc[2 * kk2][2] - mn1,     sc[2 * kk2][3] - mn1);
            p[2] = exp2_f16x2(sc[2 * kk2 + 1][0] - mn0, sc[2 * kk2 + 1][1] - mn0);
            p[3] = exp2_f16x2(sc[2 * kk2 + 1][2] - mn1, sc[2 * kk2 + 1][3] - mn1);

            // row sums: B = all ones -> every c column = sum_k P[r][k]
            mma16816(sumacc, p, ONES_H2, ONES_H2);

            uint32_t vf[4][4];
            int g = lane >> 3;
            int row = kk2 * 16 + (g & 1) * 8 + (lane & 7);
#pragma unroll
            for (int g4 = 0; g4 < 4; g4++) {
                int c16 = g4 * 2 + (g >> 1);
                uint32_t off = (uint32_t)(row * 128 + ((c16 ^ (row & 7)) * 16));
                LDSM_X4_T(vf[g4][0], vf[g4][1], vf[g4][2], vf[g4][3],
                          kb + 8192u + off);
            }
#pragma unroll
            for (int ni = 0; ni < 8; ni++) {
                const int g4 = ni >> 1, sub = (ni & 1) * 2;
                mma16816(O[ni], p, vf[g4][sub], vf[g4][sub + 1]);
            }
        }
        l0 = l0 * alpha0 + sumacc[0];
        l1 = l1 * alpha1 + sumacc[2];

        if (++buf >= 3) buf = 0;
    }

    // ---- epilogue: normalize, convert fp16, store ----
    const float inv0 = 1.f / l0;
    const float inv1 = 1.f / l1;
    const int sA = q0 + wid * 16 + (lane >> 2);
    const size_t rowA = (size_t)(sA * 2 + b) * EMBED;
    const size_t rowB = (size_t)((sA + 8) * 2 + b) * EMBED;
    const int colb = h * HDIM + (lane & 3) * 2;
#pragma unroll
    for (int ni = 0; ni < 8; ni++) {
        const int col = colb + ni * 8;
        *(uint32_t*)&oh[rowA + col] = pack_f16(O[ni][0] * inv0, O[ni][1] * inv0);
        *(uint32_t*)&oh[rowB + col] = pack_f16(O[ni][2] * inv1, O[ni][3] * inv1);
    }
}

// ---------------------------------------------------------------------------
extern "C" void kernel_launch(void* const* d_in, const int* in_sizes, int n_in,
                              void* d_out, int out_size)
{
    (void)in_sizes; (void)n_in; (void)out_size;
    const float* x    = (const float*)d_in[0];
    const float* Win  = (const float*)d_in[1];
    const float* bin  = (const float*)d_in[2];
    const float* Wout = (const float*)d_in[3];
    const float* bout = (const float*)d_in[4];
    float* out = (float*)d_out;

    __half *xh, *w1h, *w2h, *qkvh, *ah;
    cudaGetSymbolAddress((void**)&xh, g_xh);
    cudaGetSymbolAddress((void**)&w1h, g_w1h);
    cudaGetSymbolAddress((void**)&w2h, g_w2h);
    cudaGetSymbolAddress((void**)&qkvh, g_qkvh);
    cudaGetSymbolAddress((void**)&ah, g_ah);

    cudaFuncSetAttribute(gemm_mma_kernel,
                         cudaFuncAttributeMaxDynamicSharedMemorySize, GEMM_SMEM);
    cudaFuncSetAttribute(flash_mma_kernel,
                         cudaFuncAttributeMaxDynamicSharedMemorySize, FL_SMEM);

    // 0) fused fp32 -> fp16 converts (single launch)
    cvt_all_kernel<<<CVT_TOT / 256, 256>>>(
        (const float4*)x, (const float4*)Win, (const float4*)Wout,
        (uint2*)xh, (uint2*)w1h, (uint2*)w2h);

    // 1) QKV projection -> fp16 qkv (Q pre-scaled by 0.125*log2e)
    //    persistent: 384 tiles (12 cols x 32 rows), grid 148
    {
        int ntiles = (QKV_COLS / 256) * (M_ROWS / 128);   // 384
        int grid = ntiles < 148 ? ntiles : 148;
        gemm_mma_kernel<<<grid, 512, GEMM_SMEM>>>(
            xh, w1h, bin, nullptr, qkvh, QKV_COLS, EMBED, ntiles, QKV_COLS / 256);
    }

    // 2) Flash attention on tensor cores -> fp16 attn
    flash_mma_kernel<<<dim3(S_LEN / 128, BATCH * HEADS), 256, FL_SMEM>>>(
        qkvh, ah);

    // 3) Output projection -> fp32 out (128 tiles, fits one wave)
    {
        int ntiles = (EMBED / 256) * (M_ROWS / 128);      // 128
        int grid = ntiles < 148 ? ntiles : 148;
        gemm_mma_kernel<<<grid, 512, GEMM_SMEM>>>(
            ah, w2h, bout, out, nullptr, EMBED, 0, ntiles, EMBED / 256);
    }
}

// round 12
// speedup vs baseline: 1.5970x; 1.5970x over previous
#include <cuda_runtime.h>
#include <cuda_fp16.h>
#include <cstdint>

// Problem constants
#define S_LEN 2048
#define BATCH 2
#define EMBED 1024
#define HEADS 16
#define HDIM  64
#define M_ROWS (S_LEN * BATCH)        // 4096
#define QKV_COLS (3 * EMBED)          // 3072

// Q scale folded with log2(e) so softmax can use exp2 directly
#define QSCALE 0.18033688011112042f   // 0.125 * log2(e)
#define ONES_H2 0x3C003C00u           // half2(1.0, 1.0)

// ---------------------------------------------------------------------------
// Scratch (device globals; no allocation in kernel_launch)
// ---------------------------------------------------------------------------
__device__ __align__(16) __half g_xh[(size_t)M_ROWS * EMBED];
__device__ __align__(16) __half g_w1h[(size_t)QKV_COLS * EMBED];
__device__ __align__(16) __half g_w2h[(size_t)EMBED * EMBED];
__device__ __align__(16) __half g_qkvh[(size_t)M_ROWS * QKV_COLS];
__device__ __align__(16) __half g_ah[(size_t)M_ROWS * EMBED];

// ---------------------------------------------------------------------------
// PTX helpers (baseline compute_103-safe: mma.sync + ldmatrix + cp.async)
// ---------------------------------------------------------------------------
__device__ __forceinline__ uint32_t smem_u32(const void* p) {
    uint32_t addr;
    asm("{ .reg .u64 t; cvta.to.shared.u64 t, %1; cvt.u32.u64 %0, t; }"
        : "=r"(addr) : "l"(p));
    return addr;
}

__device__ __forceinline__ void cp16(uint32_t dst, const void* src) {
    asm volatile("cp.async.cg.shared.global [%0], [%1], 16;" :: "r"(dst), "l"(src));
}
#define CP_COMMIT() asm volatile("cp.async.commit_group;" ::: "memory")
#define CP_WAIT1()  asm volatile("cp.async.wait_group 1;" ::: "memory")
#define CP_WAIT2()  asm volatile("cp.async.wait_group 2;" ::: "memory")

#define LDSM_X4(r0, r1, r2, r3, addr) \
    asm volatile("ldmatrix.sync.aligned.m8n8.x4.shared.b16 {%0,%1,%2,%3}, [%4];" \
        : "=r"(r0), "=r"(r1), "=r"(r2), "=r"(r3) : "r"(addr))

#define LDSM_X4_T(r0, r1, r2, r3, addr) \
    asm volatile("ldmatrix.sync.aligned.m8n8.x4.trans.shared.b16 {%0,%1,%2,%3}, [%4];" \
        : "=r"(r0), "=r"(r1), "=r"(r2), "=r"(r3) : "r"(addr))

__device__ __forceinline__ void mma16816(float* c, const uint32_t* a,
                                         const uint32_t b0, const uint32_t b1) {
    asm volatile(
        "mma.sync.aligned.m16n8k16.row.col.f32.f16.f16.f32 "
        "{%0,%1,%2,%3}, {%4,%5,%6,%7}, {%8,%9}, {%0,%1,%2,%3};"
        : "+f"(c[0]), "+f"(c[1]), "+f"(c[2]), "+f"(c[3])
        : "r"(a[0]), "r"(a[1]), "r"(a[2]), "r"(a[3]), "r"(b0), "r"(b1));
}

__device__ __forceinline__ float fast_exp2(float x) {
    float y;
    asm("ex2.approx.f32 %0, %1;" : "=f"(y) : "f"(x));
    return y;
}

__device__ __forceinline__ uint32_t pack_f16(float f0, float f1) {
    __half2 h = __floats2half2_rn(f0, f1);
    return *reinterpret_cast<uint32_t*>(&h);
}

// pack two fp32 and take exp2 in half2 (one cvt + one MUFU for 2 elements)
__device__ __forceinline__ uint32_t exp2_f16x2(float f0, float f1) {
    uint32_t h = pack_f16(f0, f1);
    uint32_t y;
    asm("ex2.approx.f16x2 %0, %1;" : "=r"(y) : "r"(h));
    return y;
}

// ---------------------------------------------------------------------------
// fused fp32 -> fp16 convert for x, Win, Wout in ONE launch
// sizes in float4 units: x 1048576, w1 786432, w2 262144
// ---------------------------------------------------------------------------
#define CVT_X4  1048576
#define CVT_W14 786432
#define CVT_W24 262144
#define CVT_TOT (CVT_X4 + CVT_W14 + CVT_W24)   // 2097152

__global__ __launch_bounds__(256) void cvt_all_kernel(
    const float4* __restrict__ x, const float4* __restrict__ w1,
    const float4* __restrict__ w2, uint2* __restrict__ xh,
    uint2* __restrict__ w1h, uint2* __restrict__ w2h)
{
    int i = blockIdx.x * blockDim.x + threadIdx.x;
    const float4* in;
    uint2* out;
    int j;
    if (i < CVT_X4) {
        in = x; out = xh; j = i;
    } else if (i < CVT_X4 + CVT_W14) {
        in = w1; out = w1h; j = i - CVT_X4;
    } else {
        in = w2; out = w2h; j = i - CVT_X4 - CVT_W14;
    }
    float4 v = in[j];
    uint2 r;
    r.x = pack_f16(v.x, v.y);
    r.y = pack_f16(v.z, v.w);
    out[j] = r;
}

// ---------------------------------------------------------------------------
// mma.sync fp16 GEMM:  C[M,Ntot] = A[M,1024] * W[Ntot,1024]^T + bias
// CTA tile 128x256, 16 warps (4 M x 4 N), warp tile 32x64, 512 threads.
// K staged 64 elems; 3-buffer cp.async ring, ONE barrier per stage.
// grid = (Ntot/256, M/128).  Columns < qcols scaled by QSCALE.
// (round-9 proven config)
// ---------------------------------------------------------------------------
#define GK 1024
#define KSTEP 64
#define NSTAGE (GK / KSTEP)          // 16
#define STAGE_BYTES 49152            // A 16KB + W 32KB
#define GEMM_SMEM (3 * STAGE_BYTES)  // 147456

__global__ __launch_bounds__(512, 1) void gemm_mma_kernel(
    const __half* __restrict__ A, const __half* __restrict__ W,
    const float* __restrict__ bias, float* __restrict__ Cf,
    __half* __restrict__ Ch, int Ntot, int qcols)
{
    extern __shared__ char sm_raw[];
    const uint32_t smem_base = smem_u32(sm_raw);
    const int tid = threadIdx.x;
    const int wid = tid >> 5;
    const int lane = tid & 31;
    const int warpM = wid & 3;          // 4 warps over M (32 rows each)
    const int warpN = wid >> 2;         // 4 warps over N (64 cols each)
    const int rowBase = blockIdx.y * 128;
    const int colBase = blockIdx.x * 256;

    auto load_stage = [&](int s, int buf) {
        const int k0 = s * KSTEP;
        const uint32_t base = smem_base + (uint32_t)buf * STAGE_BYTES;
#pragma unroll
        for (int i = 0; i < 6; i++) {
            int idx = tid + (i << 9);          // 0..3071
            if (idx < 1024) {
                int r = idx >> 3, c16 = idx & 7;
                const void* src = A + (size_t)(rowBase + r) * GK + k0 + c16 * 8;
                cp16(base + (uint32_t)(r * 128 + ((c16 ^ (r & 7)) * 16)), src);
            } else {
                int idx2 = idx - 1024;         // 0..2047
                int r = idx2 >> 3, c16 = idx2 & 7;
                const void* src = W + (size_t)(colBase + r) * GK + k0 + c16 * 8;
                cp16(base + 16384u + (uint32_t)(r * 128 + ((c16 ^ (r & 7)) * 16)),
                     src);
            }
        }
    };

    float acc[2][8][4];
#pragma unroll
    for (int mi = 0; mi < 2; mi++)
#pragma unroll
        for (int ni = 0; ni < 8; ni++)
#pragma unroll
            for (int j = 0; j < 4; j++) acc[mi][ni][j] = 0.f;

    const int aRow = warpM * 32 + (lane & 15);
    const int aHalf = lane >> 4;
    const int bRow = warpN * 64 + ((lane >> 4) * 8) + (lane & 7);
    const int bHalf = (lane >> 3) & 1;

    load_stage(0, 0); CP_COMMIT();
    load_stage(1, 1); CP_COMMIT();

    int buf = 0;
    for (int s = 0; s < NSTAGE; s++) {
        CP_WAIT1();
        __syncthreads();
        if (s + 2 < NSTAGE) {
            int nbuf = buf + 2; if (nbuf >= 3) nbuf -= 3;
            load_stage(s + 2, nbuf);
            CP_COMMIT();
        }

        const uint32_t base = smem_base + (uint32_t)buf * STAGE_BYTES;
#pragma unroll
        for (int kk = 0; kk < 4; kk++) {
            uint32_t a[2][4], b[4][4];
#pragma unroll
            for (int mi = 0; mi < 2; mi++) {
                int r = aRow + mi * 16;
                int c16 = kk * 2 + aHalf;
                uint32_t off = (uint32_t)(r * 128 + ((c16 ^ (r & 7)) * 16));
                LDSM_X4(a[mi][0], a[mi][1], a[mi][2], a[mi][3], base + off);
            }
#pragma unroll
            for (int np = 0; np < 4; np++) {
                int r = bRow + np * 16;
                int c16 = kk * 2 + bHalf;
                uint32_t off = (uint32_t)(r * 128 + ((c16 ^ (r & 7)) * 16));
                LDSM_X4(b[np][0], b[np][1], b[np][2], b[np][3],
                        base + 16384u + off);
            }
#pragma unroll
            for (int mi = 0; mi < 2; mi++)
#pragma unroll
                for (int ni = 0; ni < 8; ni++) {
                    const int np = ni >> 1, sub = (ni & 1) * 2;
                    mma16816(acc[mi][ni], a[mi], b[np][sub], b[np][sub + 1]);
                }
        }
        if (++buf >= 3) buf = 0;
    }

    const int erow = rowBase + warpM * 32 + (lane >> 2);
    const int ecol0 = colBase + warpN * 64 + (lane & 3) * 2;
#pragma unroll
    for (int ni = 0; ni < 8; ni++) {
        const int col = ecol0 + ni * 8;
        const float sc = (col < qcols) ? QSCALE : 1.f;
        const float bx = bias[col], by = bias[col + 1];
#pragma unroll
        for (int mi = 0; mi < 2; mi++) {
            const int r0 = erow + mi * 16;
            float v0 = (acc[mi][ni][0] + bx) * sc;
            float v1 = (acc[mi][ni][1] + by) * sc;
            float v2 = (acc[mi][ni][2] + bx) * sc;
            float v3 = (acc[mi][ni][3] + by) * sc;
            if (Cf) {
                *(float2*)&Cf[(size_t)r0 * Ntot + col] = make_float2(v0, v1);
                *(float2*)&Cf[(size_t)(r0 + 8) * Ntot + col] = make_float2(v2, v3);
            } else {
                *(uint32_t*)&Ch[(size_t)r0 * Ntot + col] = pack_f16(v0, v1);
                *(uint32_t*)&Ch[(size_t)(r0 + 8) * Ntot + col] = pack_f16(v2, v3);
            }
        }
    }
}

// ---------------------------------------------------------------------------
// Flash attention on mma.sync fp16, exp2 in f16x2, row-sums via ones-MMA.
// grid (S/128, B*H), 256 threads (8 warps x 16 q rows each).
// KV chunk = 64 rows; 3-buffer cp.async ring, ONE barrier per chunk.
// smem 64KB; __launch_bounds__(256,2) targets 2 CTAs/SM (<=128 regs).
// (round-9 proven config)
// ---------------------------------------------------------------------------
#define FL_SMEM 65536
#define NCHUNK (S_LEN / 64)   // 32

__global__ __launch_bounds__(256, 2) void flash_mma_kernel(
    const __half* __restrict__ qkv, __half* __restrict__ oh)
{
    extern __shared__ char sm_raw[];
    const uint32_t sb = smem_u32(sm_raw);
    const int tid = threadIdx.x;
    const int wid = tid >> 5;
    const int lane = tid & 31;
    const int q0 = blockIdx.x * 128;
    const int b = blockIdx.y >> 4;
    const int h = blockIdx.y & 15;
    const int qcol = h * HDIM;
    const int kcol = EMBED + h * HDIM;
    const int vcol = 2 * EMBED + h * HDIM;

    // ---- load Q tile: 1024 cp16 (group 0) ----
#pragma unroll
    for (int i = 0; i < 4; i++) {
        int idx = tid + (i << 8);
        int r = idx >> 3;
        int c16 = idx & 7;
        const void* src = qkv + (size_t)((q0 + r) * 2 + b) * QKV_COLS + qcol + c16 * 8;
        cp16(sb + (uint32_t)(r * 128 + ((c16 ^ (r & 7)) * 16)), src);
    }
    CP_COMMIT();

    auto load_kv = [&](int j0, int buf) {
        const uint32_t base = sb + 16384u + (uint32_t)buf * 16384u;
#pragma unroll
        for (int i = 0; i < 4; i++) {
            int idx = tid + (i << 8);
            int mat = idx >> 9;             // 0:K 1:V
            int r = (idx >> 3) & 63;
            int c16 = idx & 7;
            int colb = mat ? vcol : kcol;
            const void* src = qkv + (size_t)((j0 + r) * 2 + b) * QKV_COLS + colb + c16 * 8;
            uint32_t dst = base + (uint32_t)(mat * 8192 + r * 128 +
                                             ((c16 ^ (r & 7)) * 16));
            cp16(dst, src);
        }
    };

    load_kv(0, 0);  CP_COMMIT();
    load_kv(64, 1); CP_COMMIT();

    CP_WAIT2();      // Q resident
    __syncthreads();

    // ---- Q fragments into registers ----
    uint32_t aq[4][4];
    {
        int r = wid * 16 + (lane & 15);
#pragma unroll
        for (int kk = 0; kk < 4; kk++) {
            int c16 = kk * 2 + (lane >> 4);
            uint32_t off = (uint32_t)(r * 128 + ((c16 ^ (r & 7)) * 16));
            LDSM_X4(aq[kk][0], aq[kk][1], aq[kk][2], aq[kk][3], sb + off);
        }
    }

    float O[8][4];
#pragma unroll
    for (int ni = 0; ni < 8; ni++)
#pragma unroll
        for (int j = 0; j < 4; j++) O[ni][j] = 0.f;
    float m0 = -1e30f, m1 = -1e30f, l0 = 0.f, l1 = 0.f;

    int buf = 0;
    for (int s = 0; s < NCHUNK; s++) {
        CP_WAIT1();
        __syncthreads();
        if (s + 2 < NCHUNK) {
            int nbuf = buf + 2; if (nbuf >= 3) nbuf -= 3;
            load_kv((s + 2) * 64, nbuf);
            CP_COMMIT();
        }

        const uint32_t kb = sb + 16384u + (uint32_t)buf * 16384u;

        // ---- QK^T ----
        float sc[8][4];
#pragma unroll
        for (int ni = 0; ni < 8; ni++)
#pragma unroll
            for (int j = 0; j < 4; j++) sc[ni][j] = 0.f;

#pragma unroll
        for (int kk = 0; kk < 4; kk++) {
            uint32_t kf[4][4];
            int rb = ((lane >> 4) * 8) + (lane & 7);
            int c16 = kk * 2 + ((lane >> 3) & 1);
#pragma unroll
            for (int np = 0; np < 4; np++) {
                int r = rb + np * 16;
                uint32_t off = (uint32_t)(r * 128 + ((c16 ^ (r & 7)) * 16));
                LDSM_X4(kf[np][0], kf[np][1], kf[np][2], kf[np][3], kb + off);
            }
#pragma unroll
            for (int ni = 0; ni < 8; ni++) {
                const int np = ni >> 1, sub = (ni & 1) * 2;
                mma16816(sc[ni], aq[kk], kf[np][sub], kf[np][sub + 1]);
            }
        }

        // ---- max/alpha bookkeeping (fp32) ----
        float mn0, mn1, alpha0, alpha1;
        {
            float mx = -1e30f;
#pragma unroll
            for (int ni = 0; ni < 8; ni++)
                mx = fmaxf(mx, fmaxf(sc[ni][0], sc[ni][1]));
            mx = fmaxf(mx, __shfl_xor_sync(0xffffffffu, mx, 1));
            mx = fmaxf(mx, __shfl_xor_sync(0xffffffffu, mx, 2));
            mn0 = fmaxf(m0, mx);
            alpha0 = fast_exp2(m0 - mn0);
            m0 = mn0;
        }
        {
            float mx = -1e30f;
#pragma unroll
            for (int ni = 0; ni < 8; ni++)
                mx = fmaxf(mx, fmaxf(sc[ni][2], sc[ni][3]));
            mx = fmaxf(mx, __shfl_xor_sync(0xffffffffu, mx, 1));
            mx = fmaxf(mx, __shfl_xor_sync(0xffffffffu, mx, 2));
            mn1 = fmaxf(m1, mx);
            alpha1 = fast_exp2(m1 - mn1);
            m1 = mn1;
        }
#pragma unroll
        for (int ni = 0; ni < 8; ni++) {
            O[ni][0] *= alpha0; O[ni][1] *= alpha0;
            O[ni][2] *= alpha1; O[ni][3] *= alpha1;
        }

        // ---- P (fp16 exp2) @ V, row sums via ones-MMA ----
        float sumacc[4] = {0.f, 0.f, 0.f, 0.f};
#pragma unroll
        for (int kk2 = 0; kk2 < 4; kk2++) {
            uint32_t p[4];
            p[0] = exp2_f16x2(sc[2 * kk2][0] - mn0,     sc[2 * kk2][1] - mn0);
            p[1] = exp2_f16x2(sc[2 * kk2][2] - mn1,     sc[2 * kk2][3] - mn1);
            p[2] = exp2_f16x2(sc[2 * kk2 + 1][0] - mn0, sc[2 * kk2 + 1][1] - mn0);
            p[3] = exp2_f16x2(sc[2 * kk2 + 1][2] - mn1, sc[2 * kk2 + 1][3] - mn1);

            // row sums: B = all ones -> every c column = sum_k P[r][k]
            mma16816(sumacc, p, ONES_H2, ONES_H2);

            uint32_t vf[4][4];
            int g = lane >> 3;
            int row = kk2 * 16 + (g & 1) * 8 + (lane & 7);
#pragma unroll
            for (int g4 = 0; g4 < 4; g4++) {
                int c16 = g4 * 2 + (g >> 1);
                uint32_t off = (uint32_t)(row * 128 + ((c16 ^ (row & 7)) * 16));
                LDSM_X4_T(vf[g4][0], vf[g4][1], vf[g4][2], vf[g4][3],
                          kb + 8192u + off);
            }
#pragma unroll
            for (int ni = 0; ni < 8; ni++) {
                const int g4 = ni >> 1, sub = (ni & 1) * 2;
                mma16816(O[ni], p, vf[g4][sub], vf[g4][sub + 1]);
            }
        }
        l0 = l0 * alpha0 + sumacc[0];
        l1 = l1 * alpha1 + sumacc[2];

        if (++buf >= 3) buf = 0;
    }

    // ---- epilogue: normalize, convert fp16, store ----
    const float inv0 = 1.f / l0;
    const float inv1 = 1.f / l1;
    const int sA = q0 + wid * 16 + (lane >> 2);
    const size_t rowA = (size_t)(sA * 2 + b) * EMBED;
    const size_t rowB = (size_t)((sA + 8) * 2 + b) * EMBED;
    const int colb = h * HDIM + (lane & 3) * 2;
#pragma unroll
    for (int ni = 0; ni < 8; ni++) {
        const int col = colb + ni * 8;
        *(uint32_t*)&oh[rowA + col] = pack_f16(O[ni][0] * inv0, O[ni][1] * inv0);
        *(uint32_t*)&oh[rowB + col] = pack_f16(O[ni][2] * inv1, O[ni][3] * inv1);
    }
}

// ---------------------------------------------------------------------------
extern "C" void kernel_launch(void* const* d_in, const int* in_sizes, int n_in,
                              void* d_out, int out_size)
{
    (void)in_sizes; (void)n_in; (void)out_size;
    const float* x    = (const float*)d_in[0];
    const float* Win  = (const float*)d_in[1];
    const float* bin  = (const float*)d_in[2];
    const float* Wout = (const float*)d_in[3];
    const float* bout = (const float*)d_in[4];
    float* out = (float*)d_out;

    __half *xh, *w1h, *w2h, *qkvh, *ah;
    cudaGetSymbolAddress((void**)&xh, g_xh);
    cudaGetSymbolAddress((void**)&w1h, g_w1h);
    cudaGetSymbolAddress((void**)&w2h, g_w2h);
    cudaGetSymbolAddress((void**)&qkvh, g_qkvh);
    cudaGetSymbolAddress((void**)&ah, g_ah);

    cudaFuncSetAttribute(gemm_mma_kernel,
                         cudaFuncAttributeMaxDynamicSharedMemorySize, GEMM_SMEM);
    cudaFuncSetAttribute(flash_mma_kernel,
                         cudaFuncAttributeMaxDynamicSharedMemorySize, FL_SMEM);

    // 0) fused fp32 -> fp16 converts (single launch)
    cvt_all_kernel<<<CVT_TOT / 256, 256>>>(
        (const float4*)x, (const float4*)Win, (const float4*)Wout,
        (uint2*)xh, (uint2*)w1h, (uint2*)w2h);

    // 1) QKV projection -> fp16 qkv (Q pre-scaled by 0.125*log2e)
    gemm_mma_kernel<<<dim3(QKV_COLS / 256, M_ROWS / 128), 512, GEMM_SMEM>>>(
        xh, w1h, bin, nullptr, qkvh, QKV_COLS, EMBED);

    // 2) Flash attention on tensor cores -> fp16 attn
    flash_mma_kernel<<<dim3(S_LEN / 128, BATCH * HEADS), 256, FL_SMEM>>>(
        qkvh, ah);

    // 3) Output projection -> fp32 out
    gemm_mma_kernel<<<dim3(EMBED / 256, M_ROWS / 128), 512, GEMM_SMEM>>>(
        ah, w2h, bout, out, nullptr, EMBED, 0);
}

// round 13
// speedup vs baseline: 1.5997x; 1.0017x over previous
#include <cuda_runtime.h>
#include <cuda_fp16.h>
#include <cstdint>

// Problem constants
#define S_LEN 2048
#define BATCH 2
#define EMBED 1024
#define HEADS 16
#define HDIM  64
#define M_ROWS (S_LEN * BATCH)        // 4096
#define QKV_COLS (3 * EMBED)          // 3072

// Q scale folded with log2(e) so softmax can use exp2 directly
#define QSCALE 0.18033688011112042f   // 0.125 * log2(e)
#define ONES_H2 0x3C003C00u           // half2(1.0, 1.0)

// ---------------------------------------------------------------------------
// Scratch (device globals; no allocation in kernel_launch)
// ---------------------------------------------------------------------------
__device__ __align__(16) __half g_xh[(size_t)M_ROWS * EMBED];
__device__ __align__(16) __half g_w1h[(size_t)QKV_COLS * EMBED];
__device__ __align__(16) __half g_w2h[(size_t)EMBED * EMBED];
__device__ __align__(16) __half g_qkvh[(size_t)M_ROWS * QKV_COLS];
__device__ __align__(16) __half g_ah[(size_t)M_ROWS * EMBED];

// ---------------------------------------------------------------------------
// PTX helpers (baseline compute_103-safe: mma.sync + ldmatrix + cp.async)
// ---------------------------------------------------------------------------
__device__ __forceinline__ uint32_t smem_u32(const void* p) {
    uint32_t addr;
    asm("{ .reg .u64 t; cvta.to.shared.u64 t, %1; cvt.u32.u64 %0, t; }"
        : "=r"(addr) : "l"(p));
    return addr;
}

__device__ __forceinline__ void cp16(uint32_t dst, const void* src) {
    asm volatile("cp.async.cg.shared.global [%0], [%1], 16;" :: "r"(dst), "l"(src));
}
#define CP_COMMIT() asm volatile("cp.async.commit_group;" ::: "memory")
#define CP_WAIT1()  asm volatile("cp.async.wait_group 1;" ::: "memory")
#define CP_WAIT2()  asm volatile("cp.async.wait_group 2;" ::: "memory")

#define LDSM_X4(r0, r1, r2, r3, addr) \
    asm volatile("ldmatrix.sync.aligned.m8n8.x4.shared.b16 {%0,%1,%2,%3}, [%4];" \
        : "=r"(r0), "=r"(r1), "=r"(r2), "=r"(r3) : "r"(addr))

#define LDSM_X4_T(r0, r1, r2, r3, addr) \
    asm volatile("ldmatrix.sync.aligned.m8n8.x4.trans.shared.b16 {%0,%1,%2,%3}, [%4];" \
        : "=r"(r0), "=r"(r1), "=r"(r2), "=r"(r3) : "r"(addr))

__device__ __forceinline__ void mma16816(float* c, const uint32_t* a,
                                         const uint32_t b0, const uint32_t b1) {
    asm volatile(
        "mma.sync.aligned.m16n8k16.row.col.f32.f16.f16.f32 "
        "{%0,%1,%2,%3}, {%4,%5,%6,%7}, {%8,%9}, {%0,%1,%2,%3};"
        : "+f"(c[0]), "+f"(c[1]), "+f"(c[2]), "+f"(c[3])
        : "r"(a[0]), "r"(a[1]), "r"(a[2]), "r"(a[3]), "r"(b0), "r"(b1));
}

__device__ __forceinline__ float fast_exp2(float x) {
    float y;
    asm("ex2.approx.f32 %0, %1;" : "=f"(y) : "f"(x));
    return y;
}

__device__ __forceinline__ uint32_t pack_f16(float f0, float f1) {
    __half2 h = __floats2half2_rn(f0, f1);
    return *reinterpret_cast<uint32_t*>(&h);
}

// pack two fp32 and take exp2 in half2 (one cvt + one MUFU for 2 elements)
__device__ __forceinline__ uint32_t exp2_f16x2(float f0, float f1) {
    uint32_t h = pack_f16(f0, f1);
    uint32_t y;
    asm("ex2.approx.f16x2 %0, %1;" : "=r"(y) : "r"(h));
    return y;
}

// ---------------------------------------------------------------------------
// fused fp32 -> fp16 convert for x, Win, Wout in ONE launch
// ---------------------------------------------------------------------------
#define CVT_X4  1048576
#define CVT_W14 786432
#define CVT_W24 262144
#define CVT_TOT (CVT_X4 + CVT_W14 + CVT_W24)   // 2097152

__global__ __launch_bounds__(256) void cvt_all_kernel(
    const float4* __restrict__ x, const float4* __restrict__ w1,
    const float4* __restrict__ w2, uint2* __restrict__ xh,
    uint2* __restrict__ w1h, uint2* __restrict__ w2h)
{
    int i = blockIdx.x * blockDim.x + threadIdx.x;
    const float4* in;
    uint2* out;
    int j;
    if (i < CVT_X4) {
        in = x; out = xh; j = i;
    } else if (i < CVT_X4 + CVT_W14) {
        in = w1; out = w1h; j = i - CVT_X4;
    } else {
        in = w2; out = w2h; j = i - CVT_X4 - CVT_W14;
    }
    float4 v = in[j];
    uint2 r;
    r.x = pack_f16(v.x, v.y);
    r.y = pack_f16(v.z, v.w);
    out[j] = r;
}

// ---------------------------------------------------------------------------
// mma.sync fp16 GEMM:  C[M,Ntot] = A[M,1024] * W[Ntot,1024]^T + bias
// CTA tile 128x256, 16 warps (4 M x 4 N), warp tile 32x64, 512 threads.
// K staged 64 elems; 3-buffer cp.async ring, ONE barrier per stage.
// grid = (Ntot/256, M/128).  Columns < qcols scaled by QSCALE.
// (round-9/12 proven config — FROZEN)
// ---------------------------------------------------------------------------
#define GK 1024
#define KSTEP 64
#define NSTAGE (GK / KSTEP)          // 16
#define STAGE_BYTES 49152            // A 16KB + W 32KB
#define GEMM_SMEM (3 * STAGE_BYTES)  // 147456

__global__ __launch_bounds__(512, 1) void gemm_mma_kernel(
    const __half* __restrict__ A, const __half* __restrict__ W,
    const float* __restrict__ bias, float* __restrict__ Cf,
    __half* __restrict__ Ch, int Ntot, int qcols)
{
    extern __shared__ char sm_raw[];
    const uint32_t smem_base = smem_u32(sm_raw);
    const int tid = threadIdx.x;
    const int wid = tid >> 5;
    const int lane = tid & 31;
    const int warpM = wid & 3;          // 4 warps over M (32 rows each)
    const int warpN = wid >> 2;         // 4 warps over N (64 cols each)
    const int rowBase = blockIdx.y * 128;
    const int colBase = blockIdx.x * 256;

    auto load_stage = [&](int s, int buf) {
        const int k0 = s * KSTEP;
        const uint32_t base = smem_base + (uint32_t)buf * STAGE_BYTES;
#pragma unroll
        for (int i = 0; i < 6; i++) {
            int idx = tid + (i << 9);          // 0..3071
            if (idx < 1024) {
                int r = idx >> 3, c16 = idx & 7;
                const void* src = A + (size_t)(rowBase + r) * GK + k0 + c16 * 8;
                cp16(base + (uint32_t)(r * 128 + ((c16 ^ (r & 7)) * 16)), src);
            } else {
                int idx2 = idx - 1024;         // 0..2047
                int r = idx2 >> 3, c16 = idx2 & 7;
                const void* src = W + (size_t)(colBase + r) * GK + k0 + c16 * 8;
                cp16(base + 16384u + (uint32_t)(r * 128 + ((c16 ^ (r & 7)) * 16)),
                     src);
            }
        }
    };

    float acc[2][8][4];
#pragma unroll
    for (int mi = 0; mi < 2; mi++)
#pragma unroll
        for (int ni = 0; ni < 8; ni++)
#pragma unroll
            for (int j = 0; j < 4; j++) acc[mi][ni][j] = 0.f;

    const int aRow = warpM * 32 + (lane & 15);
    const int aHalf = lane >> 4;
    const int bRow = warpN * 64 + ((lane >> 4) * 8) + (lane & 7);
    const int bHalf = (lane >> 3) & 1;

    load_stage(0, 0); CP_COMMIT();
    load_stage(1, 1); CP_COMMIT();

    int buf = 0;
    for (int s = 0; s < NSTAGE; s++) {
        CP_WAIT1();
        __syncthreads();
        if (s + 2 < NSTAGE) {
            int nbuf = buf + 2; if (nbuf >= 3) nbuf -= 3;
            load_stage(s + 2, nbuf);
            CP_COMMIT();
        }

        const uint32_t base = smem_base + (uint32_t)buf * STAGE_BYTES;
#pragma unroll
        for (int kk = 0; kk < 4; kk++) {
            uint32_t a[2][4], b[4][4];
#pragma unroll
            for (int mi = 0; mi < 2; mi++) {
                int r = aRow + mi * 16;
                int c16 = kk * 2 + aHalf;
                uint32_t off = (uint32_t)(r * 128 + ((c16 ^ (r & 7)) * 16));
                LDSM_X4(a[mi][0], a[mi][1], a[mi][2], a[mi][3], base + off);
            }
#pragma unroll
            for (int np = 0; np < 4; np++) {
                int r = bRow + np * 16;
                int c16 = kk * 2 + bHalf;
                uint32_t off = (uint32_t)(r * 128 + ((c16 ^ (r & 7)) * 16));
                LDSM_X4(b[np][0], b[np][1], b[np][2], b[np][3],
                        base + 16384u + off);
            }
#pragma unroll
            for (int mi = 0; mi < 2; mi++)
#pragma unroll
                for (int ni = 0; ni < 8; ni++) {
                    const int np = ni >> 1, sub = (ni & 1) * 2;
                    mma16816(acc[mi][ni], a[mi], b[np][sub], b[np][sub + 1]);
                }
        }
        if (++buf >= 3) buf = 0;
    }

    const int erow = rowBase + warpM * 32 + (lane >> 2);
    const int ecol0 = colBase + warpN * 64 + (lane & 3) * 2;
#pragma unroll
    for (int ni = 0; ni < 8; ni++) {
        const int col = ecol0 + ni * 8;
        const float sc = (col < qcols) ? QSCALE : 1.f;
        const float bx = bias[col], by = bias[col + 1];
#pragma unroll
        for (int mi = 0; mi < 2; mi++) {
            const int r0 = erow + mi * 16;
            float v0 = (acc[mi][ni][0] + bx) * sc;
            float v1 = (acc[mi][ni][1] + by) * sc;
            float v2 = (acc[mi][ni][2] + bx) * sc;
            float v3 = (acc[mi][ni][3] + by) * sc;
            if (Cf) {
                *(float2*)&Cf[(size_t)r0 * Ntot + col] = make_float2(v0, v1);
                *(float2*)&Cf[(size_t)(r0 + 8) * Ntot + col] = make_float2(v2, v3);
            } else {
                *(uint32_t*)&Ch[(size_t)r0 * Ntot + col] = pack_f16(v0, v1);
                *(uint32_t*)&Ch[(size_t)(r0 + 8) * Ntot + col] = pack_f16(v2, v3);
            }
        }
    }
}

// ---------------------------------------------------------------------------
// Flash attention on mma.sync fp16, exp2 in f16x2, row-sums via ones-MMA.
// NEW this round: (a) interleaved max reductions (overlap SHFL latency),
// (b) O-rescale + alpha MUFU skipped when neither row-half saw a new max
//     (numerically exact: skipped block is multiply-by-1).
// grid (S/128, B*H), 256 threads; KV chunk 64; 3-buffer ring; 2 CTAs/SM.
// ---------------------------------------------------------------------------
#define FL_SMEM 65536
#define NCHUNK (S_LEN / 64)   // 32

__global__ __launch_bounds__(256, 2) void flash_mma_kernel(
    const __half* __restrict__ qkv, __half* __restrict__ oh)
{
    extern __shared__ char sm_raw[];
    const uint32_t sb = smem_u32(sm_raw);
    const int tid = threadIdx.x;
    const int wid = tid >> 5;
    const int lane = tid & 31;
    const int q0 = blockIdx.x * 128;
    const int b = blockIdx.y >> 4;
    const int h = blockIdx.y & 15;
    const int qcol = h * HDIM;
    const int kcol = EMBED + h * HDIM;
    const int vcol = 2 * EMBED + h * HDIM;

    // ---- load Q tile: 1024 cp16 (group 0) ----
#pragma unroll
    for (int i = 0; i < 4; i++) {
        int idx = tid + (i << 8);
        int r = idx >> 3;
        int c16 = idx & 7;
        const void* src = qkv + (size_t)((q0 + r) * 2 + b) * QKV_COLS + qcol + c16 * 8;
        cp16(sb + (uint32_t)(r * 128 + ((c16 ^ (r & 7)) * 16)), src);
    }
    CP_COMMIT();

    auto load_kv = [&](int j0, int buf) {
        const uint32_t base = sb + 16384u + (uint32_t)buf * 16384u;
#pragma unroll
        for (int i = 0; i < 4; i++) {
            int idx = tid + (i << 8);
            int mat = idx >> 9;             // 0:K 1:V
            int r = (idx >> 3) & 63;
            int c16 = idx & 7;
            int colb = mat ? vcol : kcol;
            const void* src = qkv + (size_t)((j0 + r) * 2 + b) * QKV_COLS + colb + c16 * 8;
            uint32_t dst = base + (uint32_t)(mat * 8192 + r * 128 +
                                             ((c16 ^ (r & 7)) * 16));
            cp16(dst, src);
        }
    };

    load_kv(0, 0);  CP_COMMIT();
    load_kv(64, 1); CP_COMMIT();

    CP_WAIT2();      // Q resident
    __syncthreads();

    // ---- Q fragments into registers ----
    uint32_t aq[4][4];
    {
        int r = wid * 16 + (lane & 15);
#pragma unroll
        for (int kk = 0; kk < 4; kk++) {
            int c16 = kk * 2 + (lane >> 4);
            uint32_t off = (uint32_t)(r * 128 + ((c16 ^ (r & 7)) * 16));
            LDSM_X4(aq[kk][0], aq[kk][1], aq[kk][2], aq[kk][3], sb + off);
        }
    }

    float O[8][4];
#pragma unroll
    for (int ni = 0; ni < 8; ni++)
#pragma unroll
        for (int j = 0; j < 4; j++) O[ni][j] = 0.f;
    float m0 = -1e30f, m1 = -1e30f, l0 = 0.f, l1 = 0.f;

    int buf = 0;
    for (int s = 0; s < NCHUNK; s++) {
        CP_WAIT1();
        __syncthreads();
        if (s + 2 < NCHUNK) {
            int nbuf = buf + 2; if (nbuf >= 3) nbuf -= 3;
            load_kv((s + 2) * 64, nbuf);
            CP_COMMIT();
        }

        const uint32_t kb = sb + 16384u + (uint32_t)buf * 16384u;

        // ---- QK^T ----
        float sc[8][4];
#pragma unroll
        for (int ni = 0; ni < 8; ni++)
#pragma unroll
            for (int j = 0; j < 4; j++) sc[ni][j] = 0.f;

#pragma unroll
        for (int kk = 0; kk < 4; kk++) {
            uint32_t kf[4][4];
            int rb = ((lane >> 4) * 8) + (lane & 7);
            int c16 = kk * 2 + ((lane >> 3) & 1);
#pragma unroll
            for (int np = 0; np < 4; np++) {
                int r = rb + np * 16;
                uint32_t off = (uint32_t)(r * 128 + ((c16 ^ (r & 7)) * 16));
                LDSM_X4(kf[np][0], kf[np][1], kf[np][2], kf[np][3], kb + off);
            }
#pragma unroll
            for (int ni = 0; ni < 8; ni++) {
                const int np = ni >> 1, sub = (ni & 1) * 2;
                mma16816(sc[ni], aq[kk], kf[np][sub], kf[np][sub + 1]);
            }
        }

        // ---- max reductions (interleaved: SHFL latencies overlap) ----
        float mx0 = -1e30f, mx1 = -1e30f;
#pragma unroll
        for (int ni = 0; ni < 8; ni++) {
            mx0 = fmaxf(mx0, fmaxf(sc[ni][0], sc[ni][1]));
            mx1 = fmaxf(mx1, fmaxf(sc[ni][2], sc[ni][3]));
        }
        {
            float t0 = __shfl_xor_sync(0xffffffffu, mx0, 1);
            float t1 = __shfl_xor_sync(0xffffffffu, mx1, 1);
            mx0 = fmaxf(mx0, t0);
            mx1 = fmaxf(mx1, t1);
            t0 = __shfl_xor_sync(0xffffffffu, mx0, 2);
            t1 = __shfl_xor_sync(0xffffffffu, mx1, 2);
            mx0 = fmaxf(mx0, t0);
            mx1 = fmaxf(mx1, t1);
        }
        const float mn0 = fmaxf(m0, mx0);
        const float mn1 = fmaxf(m1, mx1);

        // ---- rescale only when a new max appeared (exact skip) ----
        if (mx0 > m0 || mx1 > m1) {
            const float alpha0 = fast_exp2(m0 - mn0);
            const float alpha1 = fast_exp2(m1 - mn1);
#pragma unroll
            for (int ni = 0; ni < 8; ni++) {
                O[ni][0] *= alpha0; O[ni][1] *= alpha0;
                O[ni][2] *= alpha1; O[ni][3] *= alpha1;
            }
            l0 *= alpha0;
            l1 *= alpha1;
        }
        m0 = mn0;
        m1 = mn1;

        // ---- P (fp16 exp2) @ V, row sums via ones-MMA ----
        float sumacc[4] = {0.f, 0.f, 0.f, 0.f};
#pragma unroll
        for (int kk2 = 0; kk2 < 4; kk2++) {
            uint32_t p[4];
            p[0] = exp2_f16x2(sc[2 * kk2][0] - mn0,     sc[2 * kk2][1] - mn0);
            p[1] = exp2_f16x2(sc[2 * kk2][2] - mn1,     sc[2 * kk2][3] - mn1);
            p[2] = exp2_f16x2(sc[2 * kk2 + 1][0] - mn0, sc[2 * kk2 + 1][1] - mn0);
            p[3] = exp2_f16x2(sc[2 * kk2 + 1][2] - mn1, sc[2 * kk2 + 1][3] - mn1);

            // row sums: B = all ones -> every c column = sum_k P[r][k]
            mma16816(sumacc, p, ONES_H2, ONES_H2);

            uint32_t vf[4][4];
            int g = lane >> 3;
            int row = kk2 * 16 + (g & 1) * 8 + (lane & 7);
#pragma unroll
            for (int g4 = 0; g4 < 4; g4++) {
                int c16 = g4 * 2 + (g >> 1);
                uint32_t off = (uint32_t)(row * 128 + ((c16 ^ (row & 7)) * 16));
                LDSM_X4_T(vf[g4][0], vf[g4][1], vf[g4][2], vf[g4][3],
                          kb + 8192u + off);
            }
#pragma unroll
            for (int ni = 0; ni < 8; ni++) {
                const int g4 = ni >> 1, sub = (ni & 1) * 2;
                mma16816(O[ni], p, vf[g4][sub], vf[g4][sub + 1]);
            }
        }
        l0 += sumacc[0];
        l1 += sumacc[2];

        if (++buf >= 3) buf = 0;
    }

    // ---- epilogue: normalize, convert fp16, store ----
    const float inv0 = 1.f / l0;
    const float inv1 = 1.f / l1;
    const int sA = q0 + wid * 16 + (lane >> 2);
    const size_t rowA = (size_t)(sA * 2 + b) * EMBED;
    const size_t rowB = (size_t)((sA + 8) * 2 + b) * EMBED;
    const int colb = h * HDIM + (lane & 3) * 2;
#pragma unroll
    for (int ni = 0; ni < 8; ni++) {
        const int col = colb + ni * 8;
        *(uint32_t*)&oh[rowA + col] = pack_f16(O[ni][0] * inv0, O[ni][1] * inv0);
        *(uint32_t*)&oh[rowB + col] = pack_f16(O[ni][2] * inv1, O[ni][3] * inv1);
    }
}

// ---------------------------------------------------------------------------
extern "C" void kernel_launch(void* const* d_in, const int* in_sizes, int n_in,
                              void* d_out, int out_size)
{
    (void)in_sizes; (void)n_in; (void)out_size;
    const float* x    = (const float*)d_in[0];
    const float* Win  = (const float*)d_in[1];
    const float* bin  = (const float*)d_in[2];
    const float* Wout = (const float*)d_in[3];
    const float* bout = (const float*)d_in[4];
    float* out = (float*)d_out;

    __half *xh, *w1h, *w2h, *qkvh, *ah;
    cudaGetSymbolAddress((void**)&xh, g_xh);
    cudaGetSymbolAddress((void**)&w1h, g_w1h);
    cudaGetSymbolAddress((void**)&w2h, g_w2h);
    cudaGetSymbolAddress((void**)&qkvh, g_qkvh);
    cudaGetSymbolAddress((void**)&ah, g_ah);

    cudaFuncSetAttribute(gemm_mma_kernel,
                         cudaFuncAttributeMaxDynamicSharedMemorySize, GEMM_SMEM);
    cudaFuncSetAttribute(flash_mma_kernel,
                         cudaFuncAttributeMaxDynamicSharedMemorySize, FL_SMEM);

    // 0) fused fp32 -> fp16 converts (single launch)
    cvt_all_kernel<<<CVT_TOT / 256, 256>>>(
        (const float4*)x, (const float4*)Win, (const float4*)Wout,
        (uint2*)xh, (uint2*)w1h, (uint2*)w2h);

    // 1) QKV projection -> fp16 qkv (Q pre-scaled by 0.125*log2e)
    gemm_mma_kernel<<<dim3(QKV_COLS / 256, M_ROWS / 128), 512, GEMM_SMEM>>>(
        xh, w1h, bin, nullptr, qkvh, QKV_COLS, EMBED);

    // 2) Flash attention on tensor cores -> fp16 attn
    flash_mma_kernel<<<dim3(S_LEN / 128, BATCH * HEADS), 256, FL_SMEM>>>(
        qkvh, ah);

    // 3) Output projection -> fp32 out
    gemm_mma_kernel<<<dim3(EMBED / 256, M_ROWS / 128), 512, GEMM_SMEM>>>(
        ah, w2h, bout, out, nullptr, EMBED, 0);
}